// round 6
// baseline (speedup 1.0000x reference)
#include <cuda_runtime.h>
#include <cuda_bf16.h>
#include <math.h>

#define N_NODES 100000
#define F_IN    1433
#define F_H     32
#define F_OUT   7
#define E_MAX   3400000

// ---------------- scratch (static device globals; no allocation) ----------------
__device__ float g_dinv[N_NODES];
__device__ float g_h   [N_NODES * F_H];     // (x @ W1) * dinv[row]
__device__ float g_h2  [N_NODES * 8];       // (h1 @ W2) * dinv[row], padded 7->8
__device__ int   g_count [N_NODES];
__device__ int   g_row   [N_NODES + 1];
__device__ int   g_cursor[N_NODES];
__device__ int   g_ssrc  [E_MAX];

__device__ __forceinline__ void mma_tf32(float* d, const unsigned* a, const unsigned* b) {
    asm volatile(
        "mma.sync.aligned.m16n8k8.row.col.f32.tf32.tf32.f32 "
        "{%0,%1,%2,%3}, {%4,%5,%6,%7}, {%8,%9}, {%0,%1,%2,%3};"
        : "+f"(d[0]), "+f"(d[1]), "+f"(d[2]), "+f"(d[3])
        : "r"(a[0]), "r"(a[1]), "r"(a[2]), "r"(a[3]), "r"(b[0]), "r"(b[1]));
}

__device__ __forceinline__ void cp_async16(void* smem_dst, const void* gsrc, int src_bytes) {
    unsigned saddr = (unsigned)__cvta_generic_to_shared(smem_dst);
    asm volatile("cp.async.cg.shared.global [%0], [%1], 16, %2;"
                 :: "r"(saddr), "l"(gsrc), "r"(src_bytes) : "memory");
}
__device__ __forceinline__ void cp_commit() { asm volatile("cp.async.commit_group;" ::: "memory"); }
__device__ __forceinline__ void cp_wait1()  { asm volatile("cp.async.wait_group 1;" ::: "memory"); }
__device__ __forceinline__ void cp_wait0()  { asm volatile("cp.async.wait_group 0;" ::: "memory"); }

// ---------------- CSR build ----------------
__global__ void zero_kernel() {
    int i = blockIdx.x * blockDim.x + threadIdx.x;
    if (i < N_NODES) g_count[i] = 0;
}

__global__ void hist_kernel(const int* __restrict__ dst, int E) {
    int e = blockIdx.x * blockDim.x + threadIdx.x;
    if (e < E) atomicAdd(&g_count[dst[e]], 1);
}

// single-block scan: g_row (exclusive), g_cursor, g_dinv
__global__ __launch_bounds__(1024) void scan_kernel() {
    __shared__ int s_warp[33];
    __shared__ int s_running;
    int t = threadIdx.x;
    int lane = t & 31, wid = t >> 5;
    if (t == 0) s_running = 0;
    __syncthreads();
    for (int base = 0; base < N_NODES; base += 1024) {
        int i = base + t;
        int v = (i < N_NODES) ? g_count[i] : 0;
        int incl = v;
        #pragma unroll
        for (int off = 1; off < 32; off <<= 1) {
            int y = __shfl_up_sync(0xffffffffu, incl, off);
            if (lane >= off) incl += y;
        }
        if (lane == 31) s_warp[wid] = incl;
        __syncthreads();
        if (wid == 0) {
            int w = s_warp[lane];
            #pragma unroll
            for (int off = 1; off < 32; off <<= 1) {
                int y = __shfl_up_sync(0xffffffffu, w, off);
                if (lane >= off) w += y;
            }
            s_warp[lane] = w;
        }
        __syncthreads();
        int warpoff = (wid > 0) ? s_warp[wid - 1] : 0;
        int total = s_warp[31];
        int r = s_running + warpoff + incl - v;
        if (i < N_NODES) {
            g_row[i] = r;
            g_cursor[i] = r;
            g_dinv[i] = rsqrtf((float)(v + 1));   // +1 self loop
        }
        __syncthreads();
        if (t == 0) s_running += total;
        __syncthreads();
    }
    if (t == 0) g_row[N_NODES] = s_running;
}

__global__ void reorder_kernel(const int* __restrict__ src, const int* __restrict__ dst, int E) {
    int e = blockIdx.x * blockDim.x + threadIdx.x;
    if (e >= E) return;
    int d = dst[e];
    int pos = atomicAdd(&g_cursor[d], 1);
    g_ssrc[pos] = src[e];
}

// ---------------- GEMM1 (tf32 tensor cores): h = (x @ W1) * dinv ----------------
#define BM 128
#define BK 32
#define XPITCH 36
#define WPITCH 40
#define NCHUNK ((F_IN + BK - 1) / BK)   // 45

__global__ __launch_bounds__(128) void gemm1_kernel(
    const float* __restrict__ x, const float* __restrict__ W1)
{
    __shared__ __align__(16) float Xs[2][BM][XPITCH];
    __shared__ __align__(16) float Ws[2][BK][WPITCH];

    const int tid  = threadIdx.x;
    const int lane = tid & 31;
    const int warp = tid >> 5;
    const int gid  = lane >> 2;
    const int tig  = lane & 3;
    const int row0 = blockIdx.x * BM;
    const int sh   = gid & 3;

    float acc[2][4][4];
    #pragma unroll
    for (int m = 0; m < 2; ++m)
        #pragma unroll
        for (int n = 0; n < 4; ++n)
            #pragma unroll
            for (int r = 0; r < 4; ++r) acc[m][n][r] = 0.f;

    auto issue_stage = [&](int chunk, int buf) {
        int k0 = chunk * BK;
        #pragma unroll
        for (int i = 0; i < 8; ++i) {
            int r  = i * 16 + (tid >> 3);
            int j0 = (tid & 7) * 4;
            int grow = row0 + r;
            const float* srcp = x;
            int valid = 0;
            if (grow < N_NODES) {
                int shift = grow & 3;
                int col = k0 - shift + j0;
                int vb = (F_IN - col) * 4;
                valid = vb < 0 ? 0 : (vb > 16 ? 16 : vb);
                srcp = x + ((size_t)grow * F_IN + col);
            }
            cp_async16(&Xs[buf][r][j0], srcp, valid);
        }
        {
            int r = tid;
            int grow = row0 + r;
            const float* srcp = x;
            int valid = 0;
            int shift = grow & 3;
            if (grow < N_NODES && shift > 0) {
                int col = k0 - shift + 32;
                int vb = (F_IN - col) * 4;
                valid = vb < 0 ? 0 : (vb > 16 ? 16 : vb);
                srcp = x + ((size_t)grow * F_IN + col);
            }
            cp_async16(&Xs[buf][r][32], srcp, valid);
        }
        #pragma unroll
        for (int i = 0; i < 2; ++i) {
            int lin = i * 128 + tid;
            int kw = lin >> 3;
            int j = lin & 7;
            int gk = k0 + kw;
            int valid = (gk < F_IN) ? 16 : 0;
            const float* srcp = W1 + (size_t)(valid ? gk : 0) * F_H + j * 4;
            cp_async16(&Ws[buf][kw][j * 4], srcp, valid);
        }
    };

    issue_stage(0, 0);
    cp_commit();

    for (int c = 0; c < NCHUNK; ++c) {
        int buf = c & 1;
        bool more = (c + 1 < NCHUNK);
        if (more) { issue_stage(c + 1, buf ^ 1); cp_commit(); }
        if (more) cp_wait1(); else cp_wait0();
        __syncthreads();

        const int wr = warp * 32;
        #pragma unroll
        for (int ks = 0; ks < 4; ++ks) {
            int kb = ks * 8;
            unsigned afr[2][4];
            #pragma unroll
            for (int m = 0; m < 2; ++m) {
                int rb = wr + m * 16;
                afr[m][0] = __float_as_uint(Xs[buf][rb + gid    ][kb + tig + sh    ]);
                afr[m][1] = __float_as_uint(Xs[buf][rb + gid + 8][kb + tig + sh    ]);
                afr[m][2] = __float_as_uint(Xs[buf][rb + gid    ][kb + tig + sh + 4]);
                afr[m][3] = __float_as_uint(Xs[buf][rb + gid + 8][kb + tig + sh + 4]);
            }
            #pragma unroll
            for (int n = 0; n < 4; ++n) {
                unsigned bfr[2];
                bfr[0] = __float_as_uint(Ws[buf][kb + tig    ][n * 8 + gid]);
                bfr[1] = __float_as_uint(Ws[buf][kb + tig + 4][n * 8 + gid]);
                mma_tf32(acc[0][n], afr[0], bfr);
                mma_tf32(acc[1][n], afr[1], bfr);
            }
        }
        __syncthreads();
    }

    #pragma unroll
    for (int m = 0; m < 2; ++m) {
        int r0r = row0 + warp * 32 + m * 16 + gid;
        int r1r = r0r + 8;
        float w0 = (r0r < N_NODES) ? g_dinv[r0r] : 0.f;
        float w1 = (r1r < N_NODES) ? g_dinv[r1r] : 0.f;
        #pragma unroll
        for (int n = 0; n < 4; ++n) {
            int col = n * 8 + tig * 2;
            if (r0r < N_NODES)
                *(float2*)&g_h[(size_t)r0r * F_H + col] =
                    make_float2(acc[m][n][0] * w0, acc[m][n][1] * w0);
            if (r1r < N_NODES)
                *(float2*)&g_h[(size_t)r1r * F_H + col] =
                    make_float2(acc[m][n][2] * w1, acc[m][n][3] * w1);
        }
    }
}

// ------- gather + node1 fused: 8 threads/node -------
// agg = h_s[i] + sum_{j in edges(i)} h_s[ssrc[j]] ; h1 = relu(agg*dinv_i + b1)
// h2_s[i] = (h1 @ W2) * dinv_i
__global__ __launch_bounds__(256) void gather_node1_kernel(
    const float* __restrict__ b1, const float* __restrict__ W2)
{
    __shared__ float sW2[F_H * F_OUT];
    __shared__ float sb1[F_H];
    int tid = threadIdx.x;
    if (tid < F_H * F_OUT) sW2[tid] = W2[tid];
    if (tid < F_H)         sb1[tid] = b1[tid];
    __syncthreads();

    int i = blockIdx.x * 32 + (tid >> 3);
    int q = tid & 7;
    if (i >= N_NODES) return;

    int beg = g_row[i];
    int end = g_row[i + 1];

    float4 acc = ((const float4*)(g_h + (size_t)i * F_H))[q];   // self term
    for (int j = beg; j < end; ++j) {
        int s = __ldg(&g_ssrc[j]);
        float4 v = __ldg(((const float4*)(g_h + (size_t)s * F_H)) + q);
        acc.x += v.x; acc.y += v.y; acc.z += v.z; acc.w += v.w;
    }

    float di = g_dinv[i];
    float hv[4];
    hv[0] = fmaxf(acc.x * di + sb1[q * 4 + 0], 0.f);
    hv[1] = fmaxf(acc.y * di + sb1[q * 4 + 1], 0.f);
    hv[2] = fmaxf(acc.z * di + sb1[q * 4 + 2], 0.f);
    hv[3] = fmaxf(acc.w * di + sb1[q * 4 + 3], 0.f);

    float o[F_OUT];
    #pragma unroll
    for (int c = 0; c < F_OUT; ++c) o[c] = 0.f;
    #pragma unroll
    for (int t = 0; t < 4; ++t) {
        int f = q * 4 + t;
        #pragma unroll
        for (int c = 0; c < F_OUT; ++c)
            o[c] += hv[t] * sW2[f * F_OUT + c];
    }
    // reduce over the 8 lanes of this node (width=8 confines the shuffle)
    #pragma unroll
    for (int d = 4; d >= 1; d >>= 1)
        #pragma unroll
        for (int c = 0; c < F_OUT; ++c)
            o[c] += __shfl_down_sync(0xffffffffu, o[c], d, 8);

    if (q == 0) {
        float* outp = g_h2 + (size_t)i * 8;
        *(float4*)outp       = make_float4(o[0] * di, o[1] * di, o[2] * di, o[3] * di);
        *(float4*)(outp + 4) = make_float4(o[4] * di, o[5] * di, o[6] * di, 0.f);
    }
}

// ------- gather + final fused: 1 thread/node -------
__global__ __launch_bounds__(256) void gather_final_kernel(
    const float* __restrict__ b2, float* __restrict__ out)
{
    int i = blockIdx.x * blockDim.x + threadIdx.x;
    if (i >= N_NODES) return;
    int beg = g_row[i];
    int end = g_row[i + 1];

    const float4* selfp = (const float4*)(g_h2 + (size_t)i * 8);
    float4 a0 = selfp[0];
    float4 a1 = selfp[1];
    for (int j = beg; j < end; ++j) {
        int s = __ldg(&g_ssrc[j]);
        const float4* sp = (const float4*)(g_h2 + (size_t)s * 8);
        float4 v0 = __ldg(sp);
        float4 v1 = __ldg(sp + 1);
        a0.x += v0.x; a0.y += v0.y; a0.z += v0.z; a0.w += v0.w;
        a1.x += v1.x; a1.y += v1.y; a1.z += v1.z;
    }
    float di = g_dinv[i];
    float v[F_OUT];
    v[0] = a0.x * di + b2[0];
    v[1] = a0.y * di + b2[1];
    v[2] = a0.z * di + b2[2];
    v[3] = a0.w * di + b2[3];
    v[4] = a1.x * di + b2[4];
    v[5] = a1.y * di + b2[5];
    v[6] = a1.z * di + b2[6];
    float m = v[0];
    #pragma unroll
    for (int c = 1; c < F_OUT; ++c) m = fmaxf(m, v[c]);
    float s = 0.f;
    #pragma unroll
    for (int c = 0; c < F_OUT; ++c) s += expf(v[c] - m);
    float lse = m + logf(s);
    float* o = out + (size_t)i * F_OUT;
    #pragma unroll
    for (int c = 0; c < F_OUT; ++c) o[c] = v[c] - lse;
}

// ---------------- launch ----------------
extern "C" void kernel_launch(void* const* d_in, const int* in_sizes, int n_in,
                              void* d_out, int out_size)
{
    const float* x   = (const float*)d_in[0];
    const int*   ei  = (const int*)  d_in[1];
    const float* W1  = (const float*)d_in[2];
    const float* b1  = (const float*)d_in[3];
    const float* W2  = (const float*)d_in[4];
    const float* b2  = (const float*)d_in[5];
    float* out = (float*)d_out;

    const int E = in_sizes[1] / 2;
    const int* src = ei;
    const int* dst = ei + E;

    int nb_n = (N_NODES + 255) / 256;
    int nb_e = (E + 255) / 256;

    zero_kernel<<<nb_n, 256>>>();
    hist_kernel<<<nb_e, 256>>>(dst, E);
    scan_kernel<<<1, 1024>>>();
    reorder_kernel<<<nb_e, 256>>>(src, dst, E);

    int nb_g = (N_NODES + BM - 1) / BM;
    gemm1_kernel<<<nb_g, 128>>>(x, W1);

    int nb_gn = (N_NODES + 31) / 32;
    gather_node1_kernel<<<nb_gn, 256>>>(b1, W2);

    gather_final_kernel<<<nb_n, 256>>>(b2, out);
}

// round 7
// speedup vs baseline: 1.2600x; 1.2600x over previous
#include <cuda_runtime.h>
#include <cuda_bf16.h>
#include <math.h>

#define N_NODES 100000
#define F_IN    1433
#define F_H     32
#define F_OUT   7
#define E_MAX   3400000

#define SCAN_TILE 1024
#define NB_SCAN ((N_NODES + SCAN_TILE - 1) / SCAN_TILE)   // 98

// ---------------- scratch (static device globals; no allocation) ----------------
__device__ float g_dinv[N_NODES];
__device__ float g_h   [N_NODES * F_H];     // (x @ W1) * dinv[row]
__device__ float g_h2  [N_NODES * 8];       // (h1 @ W2) * dinv[row], padded 7->8
__device__ int   g_count [N_NODES];
__device__ int   g_row   [N_NODES + 1];
__device__ int   g_cursor[N_NODES];
__device__ int   g_ssrc  [E_MAX];
__device__ int   g_bsum  [NB_SCAN];
__device__ int   g_boff  [NB_SCAN];

__device__ __forceinline__ void mma_tf32(float* d, const unsigned* a, const unsigned* b) {
    asm volatile(
        "mma.sync.aligned.m16n8k8.row.col.f32.tf32.tf32.f32 "
        "{%0,%1,%2,%3}, {%4,%5,%6,%7}, {%8,%9}, {%0,%1,%2,%3};"
        : "+f"(d[0]), "+f"(d[1]), "+f"(d[2]), "+f"(d[3])
        : "r"(a[0]), "r"(a[1]), "r"(a[2]), "r"(a[3]), "r"(b[0]), "r"(b[1]));
}

__device__ __forceinline__ void cp_async16(void* smem_dst, const void* gsrc, int src_bytes) {
    unsigned saddr = (unsigned)__cvta_generic_to_shared(smem_dst);
    asm volatile("cp.async.cg.shared.global [%0], [%1], 16, %2;"
                 :: "r"(saddr), "l"(gsrc), "r"(src_bytes) : "memory");
}
__device__ __forceinline__ void cp_commit() { asm volatile("cp.async.commit_group;" ::: "memory"); }
__device__ __forceinline__ void cp_wait1()  { asm volatile("cp.async.wait_group 1;" ::: "memory"); }
__device__ __forceinline__ void cp_wait0()  { asm volatile("cp.async.wait_group 0;" ::: "memory"); }

// ---------------- CSR build ----------------
__global__ void zero_kernel() {
    int i = blockIdx.x * blockDim.x + threadIdx.x;
    if (i < N_NODES) g_count[i] = 0;
}

__global__ void hist_kernel(const int* __restrict__ dst, int E) {
    int e = blockIdx.x * blockDim.x + threadIdx.x;
    if (e < E) atomicAdd(&g_count[dst[e]], 1);
}

// pass A: per-block local exclusive scan of g_count (1024 elems/block, 256 thr x 4),
// writes local scan into g_row, block total into g_bsum, dinv inline.
__global__ __launch_bounds__(256) void scanA_kernel() {
    __shared__ int s_warp[8];
    int t = threadIdx.x;
    int lane = t & 31, wid = t >> 5;
    int base = blockIdx.x * SCAN_TILE + t * 4;

    int v[4];
    #pragma unroll
    for (int k = 0; k < 4; ++k) {
        int i = base + k;
        v[k] = (i < N_NODES) ? g_count[i] : 0;
    }
    int tsum = v[0] + v[1] + v[2] + v[3];

    int incl = tsum;
    #pragma unroll
    for (int off = 1; off < 32; off <<= 1) {
        int y = __shfl_up_sync(0xffffffffu, incl, off);
        if (lane >= off) incl += y;
    }
    if (lane == 31) s_warp[wid] = incl;
    __syncthreads();
    if (wid == 0 && lane < 8) {
        int w = s_warp[lane];
        #pragma unroll
        for (int off = 1; off < 8; off <<= 1) {
            int y = __shfl_up_sync(0xffu, w, off);
            if (lane >= off) w += y;
        }
        s_warp[lane] = w;
    }
    __syncthreads();
    int warpoff = (wid > 0) ? s_warp[wid - 1] : 0;
    int excl = warpoff + incl - tsum;

    int run = excl;
    #pragma unroll
    for (int k = 0; k < 4; ++k) {
        int i = base + k;
        if (i < N_NODES) {
            g_row[i]  = run;
            g_dinv[i] = rsqrtf((float)(v[k] + 1));
        }
        run += v[k];
    }
    if (t == 255) g_bsum[blockIdx.x] = s_warp[7];
}

// pass B: single block exclusive scan of 98 block sums; writes g_boff and total.
__global__ __launch_bounds__(128) void scanB_kernel() {
    int t = threadIdx.x;
    int lane = t & 31, wid = t >> 5;
    __shared__ int s_warp[4];
    int v = (t < NB_SCAN) ? g_bsum[t] : 0;
    int incl = v;
    #pragma unroll
    for (int off = 1; off < 32; off <<= 1) {
        int y = __shfl_up_sync(0xffffffffu, incl, off);
        if (lane >= off) incl += y;
    }
    if (lane == 31) s_warp[wid] = incl;
    __syncthreads();
    if (wid == 0 && lane < 4) {
        int w = s_warp[lane];
        #pragma unroll
        for (int off = 1; off < 4; off <<= 1) {
            int y = __shfl_up_sync(0xfu, w, off);
            if (lane >= off) w += y;
        }
        s_warp[lane] = w;
    }
    __syncthreads();
    int warpoff = (wid > 0) ? s_warp[wid - 1] : 0;
    if (t < NB_SCAN) g_boff[t] = warpoff + incl - v;
    if (t == 0) g_row[N_NODES] = s_warp[3];
}

// pass C: add block offsets, fill cursor.
__global__ __launch_bounds__(256) void scanC_kernel() {
    int i = blockIdx.x * blockDim.x + threadIdx.x;
    if (i >= N_NODES) return;
    int r = g_row[i] + g_boff[i >> 10];
    g_row[i] = r;
    g_cursor[i] = r;
}

__global__ void reorder_kernel(const int* __restrict__ src, const int* __restrict__ dst, int E) {
    int e = blockIdx.x * blockDim.x + threadIdx.x;
    if (e >= E) return;
    int d = dst[e];
    int pos = atomicAdd(&g_cursor[d], 1);
    g_ssrc[pos] = src[e];
}

// ---------------- GEMM1 (tf32 tensor cores): h = (x @ W1) * dinv ----------------
#define BM 128
#define BK 32
#define XPITCH 36
#define WPITCH 40
#define NCHUNK ((F_IN + BK - 1) / BK)   // 45

__global__ __launch_bounds__(128) void gemm1_kernel(
    const float* __restrict__ x, const float* __restrict__ W1)
{
    __shared__ __align__(16) float Xs[2][BM][XPITCH];
    __shared__ __align__(16) float Ws[2][BK][WPITCH];

    const int tid  = threadIdx.x;
    const int lane = tid & 31;
    const int warp = tid >> 5;
    const int gid  = lane >> 2;
    const int tig  = lane & 3;
    const int row0 = blockIdx.x * BM;
    const int sh   = gid & 3;

    float acc[2][4][4];
    #pragma unroll
    for (int m = 0; m < 2; ++m)
        #pragma unroll
        for (int n = 0; n < 4; ++n)
            #pragma unroll
            for (int r = 0; r < 4; ++r) acc[m][n][r] = 0.f;

    auto issue_stage = [&](int chunk, int buf) {
        int k0 = chunk * BK;
        #pragma unroll
        for (int i = 0; i < 8; ++i) {
            int r  = i * 16 + (tid >> 3);
            int j0 = (tid & 7) * 4;
            int grow = row0 + r;
            const float* srcp = x;
            int valid = 0;
            if (grow < N_NODES) {
                int shift = grow & 3;
                int col = k0 - shift + j0;
                int vb = (F_IN - col) * 4;
                valid = vb < 0 ? 0 : (vb > 16 ? 16 : vb);
                srcp = x + ((size_t)grow * F_IN + col);
            }
            cp_async16(&Xs[buf][r][j0], srcp, valid);
        }
        {
            int r = tid;
            int grow = row0 + r;
            const float* srcp = x;
            int valid = 0;
            int shift = grow & 3;
            if (grow < N_NODES && shift > 0) {
                int col = k0 - shift + 32;
                int vb = (F_IN - col) * 4;
                valid = vb < 0 ? 0 : (vb > 16 ? 16 : vb);
                srcp = x + ((size_t)grow * F_IN + col);
            }
            cp_async16(&Xs[buf][r][32], srcp, valid);
        }
        #pragma unroll
        for (int i = 0; i < 2; ++i) {
            int lin = i * 128 + tid;
            int kw = lin >> 3;
            int j = lin & 7;
            int gk = k0 + kw;
            int valid = (gk < F_IN) ? 16 : 0;
            const float* srcp = W1 + (size_t)(valid ? gk : 0) * F_H + j * 4;
            cp_async16(&Ws[buf][kw][j * 4], srcp, valid);
        }
    };

    issue_stage(0, 0);
    cp_commit();

    for (int c = 0; c < NCHUNK; ++c) {
        int buf = c & 1;
        bool more = (c + 1 < NCHUNK);
        if (more) { issue_stage(c + 1, buf ^ 1); cp_commit(); }
        if (more) cp_wait1(); else cp_wait0();
        __syncthreads();

        const int wr = warp * 32;
        #pragma unroll
        for (int ks = 0; ks < 4; ++ks) {
            int kb = ks * 8;
            unsigned afr[2][4];
            #pragma unroll
            for (int m = 0; m < 2; ++m) {
                int rb = wr + m * 16;
                afr[m][0] = __float_as_uint(Xs[buf][rb + gid    ][kb + tig + sh    ]);
                afr[m][1] = __float_as_uint(Xs[buf][rb + gid + 8][kb + tig + sh    ]);
                afr[m][2] = __float_as_uint(Xs[buf][rb + gid    ][kb + tig + sh + 4]);
                afr[m][3] = __float_as_uint(Xs[buf][rb + gid + 8][kb + tig + sh + 4]);
            }
            #pragma unroll
            for (int n = 0; n < 4; ++n) {
                unsigned bfr[2];
                bfr[0] = __float_as_uint(Ws[buf][kb + tig    ][n * 8 + gid]);
                bfr[1] = __float_as_uint(Ws[buf][kb + tig + 4][n * 8 + gid]);
                mma_tf32(acc[0][n], afr[0], bfr);
                mma_tf32(acc[1][n], afr[1], bfr);
            }
        }
        __syncthreads();
    }

    #pragma unroll
    for (int m = 0; m < 2; ++m) {
        int r0r = row0 + warp * 32 + m * 16 + gid;
        int r1r = r0r + 8;
        float w0 = (r0r < N_NODES) ? g_dinv[r0r] : 0.f;
        float w1 = (r1r < N_NODES) ? g_dinv[r1r] : 0.f;
        #pragma unroll
        for (int n = 0; n < 4; ++n) {
            int col = n * 8 + tig * 2;
            if (r0r < N_NODES)
                *(float2*)&g_h[(size_t)r0r * F_H + col] =
                    make_float2(acc[m][n][0] * w0, acc[m][n][1] * w0);
            if (r1r < N_NODES)
                *(float2*)&g_h[(size_t)r1r * F_H + col] =
                    make_float2(acc[m][n][2] * w1, acc[m][n][3] * w1);
        }
    }
}

// ------- gather + node1 fused: 8 threads/node, 4-way unrolled gather -------
__global__ __launch_bounds__(256) void gather_node1_kernel(
    const float* __restrict__ b1, const float* __restrict__ W2)
{
    __shared__ float sW2[F_H * F_OUT];
    __shared__ float sb1[F_H];
    int tid = threadIdx.x;
    if (tid < F_H * F_OUT) sW2[tid] = W2[tid];
    if (tid < F_H)         sb1[tid] = b1[tid];
    __syncthreads();

    int i = blockIdx.x * 32 + (tid >> 3);
    int q = tid & 7;
    if (i >= N_NODES) return;

    int beg = g_row[i];
    int end = g_row[i + 1];

    float4 acc = ((const float4*)(g_h + (size_t)i * F_H))[q];   // self term

    int j = beg;
    for (; j + 4 <= end; j += 4) {
        int s0 = __ldg(&g_ssrc[j    ]);
        int s1 = __ldg(&g_ssrc[j + 1]);
        int s2 = __ldg(&g_ssrc[j + 2]);
        int s3 = __ldg(&g_ssrc[j + 3]);
        float4 v0 = __ldg(((const float4*)(g_h + (size_t)s0 * F_H)) + q);
        float4 v1 = __ldg(((const float4*)(g_h + (size_t)s1 * F_H)) + q);
        float4 v2 = __ldg(((const float4*)(g_h + (size_t)s2 * F_H)) + q);
        float4 v3 = __ldg(((const float4*)(g_h + (size_t)s3 * F_H)) + q);
        acc.x += v0.x + v1.x + v2.x + v3.x;
        acc.y += v0.y + v1.y + v2.y + v3.y;
        acc.z += v0.z + v1.z + v2.z + v3.z;
        acc.w += v0.w + v1.w + v2.w + v3.w;
    }
    for (; j < end; ++j) {
        int s = __ldg(&g_ssrc[j]);
        float4 v = __ldg(((const float4*)(g_h + (size_t)s * F_H)) + q);
        acc.x += v.x; acc.y += v.y; acc.z += v.z; acc.w += v.w;
    }

    float di = g_dinv[i];
    float hv[4];
    hv[0] = fmaxf(acc.x * di + sb1[q * 4 + 0], 0.f);
    hv[1] = fmaxf(acc.y * di + sb1[q * 4 + 1], 0.f);
    hv[2] = fmaxf(acc.z * di + sb1[q * 4 + 2], 0.f);
    hv[3] = fmaxf(acc.w * di + sb1[q * 4 + 3], 0.f);

    float o[F_OUT];
    #pragma unroll
    for (int c = 0; c < F_OUT; ++c) o[c] = 0.f;
    #pragma unroll
    for (int t = 0; t < 4; ++t) {
        int f = q * 4 + t;
        #pragma unroll
        for (int c = 0; c < F_OUT; ++c)
            o[c] += hv[t] * sW2[f * F_OUT + c];
    }
    #pragma unroll
    for (int d = 4; d >= 1; d >>= 1)
        #pragma unroll
        for (int c = 0; c < F_OUT; ++c)
            o[c] += __shfl_down_sync(0xffffffffu, o[c], d, 8);

    if (q == 0) {
        float* outp = g_h2 + (size_t)i * 8;
        *(float4*)outp       = make_float4(o[0] * di, o[1] * di, o[2] * di, o[3] * di);
        *(float4*)(outp + 4) = make_float4(o[4] * di, o[5] * di, o[6] * di, 0.f);
    }
}

// ------- gather + final fused: 1 thread/node, 2-way unrolled -------
__global__ __launch_bounds__(256) void gather_final_kernel(
    const float* __restrict__ b2, float* __restrict__ out)
{
    int i = blockIdx.x * blockDim.x + threadIdx.x;
    if (i >= N_NODES) return;
    int beg = g_row[i];
    int end = g_row[i + 1];

    const float4* selfp = (const float4*)(g_h2 + (size_t)i * 8);
    float4 a0 = selfp[0];
    float4 a1 = selfp[1];
    int j = beg;
    for (; j + 2 <= end; j += 2) {
        int s0 = __ldg(&g_ssrc[j]);
        int s1 = __ldg(&g_ssrc[j + 1]);
        const float4* p0 = (const float4*)(g_h2 + (size_t)s0 * 8);
        const float4* p1 = (const float4*)(g_h2 + (size_t)s1 * 8);
        float4 u0 = __ldg(p0), u1 = __ldg(p0 + 1);
        float4 w0 = __ldg(p1), w1 = __ldg(p1 + 1);
        a0.x += u0.x + w0.x; a0.y += u0.y + w0.y;
        a0.z += u0.z + w0.z; a0.w += u0.w + w0.w;
        a1.x += u1.x + w1.x; a1.y += u1.y + w1.y; a1.z += u1.z + w1.z;
    }
    for (; j < end; ++j) {
        int s = __ldg(&g_ssrc[j]);
        const float4* sp = (const float4*)(g_h2 + (size_t)s * 8);
        float4 v0 = __ldg(sp);
        float4 v1 = __ldg(sp + 1);
        a0.x += v0.x; a0.y += v0.y; a0.z += v0.z; a0.w += v0.w;
        a1.x += v1.x; a1.y += v1.y; a1.z += v1.z;
    }
    float di = g_dinv[i];
    float v[F_OUT];
    v[0] = a0.x * di + b2[0];
    v[1] = a0.y * di + b2[1];
    v[2] = a0.z * di + b2[2];
    v[3] = a0.w * di + b2[3];
    v[4] = a1.x * di + b2[4];
    v[5] = a1.y * di + b2[5];
    v[6] = a1.z * di + b2[6];
    float m = v[0];
    #pragma unroll
    for (int c = 1; c < F_OUT; ++c) m = fmaxf(m, v[c]);
    float s = 0.f;
    #pragma unroll
    for (int c = 0; c < F_OUT; ++c) s += expf(v[c] - m);
    float lse = m + logf(s);
    float* o = out + (size_t)i * F_OUT;
    #pragma unroll
    for (int c = 0; c < F_OUT; ++c) o[c] = v[c] - lse;
}

// ---------------- launch ----------------
extern "C" void kernel_launch(void* const* d_in, const int* in_sizes, int n_in,
                              void* d_out, int out_size)
{
    const float* x   = (const float*)d_in[0];
    const int*   ei  = (const int*)  d_in[1];
    const float* W1  = (const float*)d_in[2];
    const float* b1  = (const float*)d_in[3];
    const float* W2  = (const float*)d_in[4];
    const float* b2  = (const float*)d_in[5];
    float* out = (float*)d_out;

    const int E = in_sizes[1] / 2;
    const int* src = ei;
    const int* dst = ei + E;

    int nb_n = (N_NODES + 255) / 256;
    int nb_e = (E + 255) / 256;

    zero_kernel<<<nb_n, 256>>>();
    hist_kernel<<<nb_e, 256>>>(dst, E);
    scanA_kernel<<<NB_SCAN, 256>>>();
    scanB_kernel<<<1, 128>>>();
    scanC_kernel<<<nb_n, 256>>>();
    reorder_kernel<<<nb_e, 256>>>(src, dst, E);

    int nb_g = (N_NODES + BM - 1) / BM;
    gemm1_kernel<<<nb_g, 128>>>(x, W1);

    int nb_gn = (N_NODES + 31) / 32;
    gather_node1_kernel<<<nb_gn, 256>>>(b1, W2);

    gather_final_kernel<<<nb_n, 256>>>(b2, out);
}